// round 8
// baseline (speedup 1.0000x reference)
#include <cuda_runtime.h>

// Problem constants
#define NCH   8192
#define NTT   4096
#define NLAGS 103
#define RAWS  112
#define XCOR_N (NCH * NLAGS)

// Stage-1 tiling: 2 channels/block (interleaved pairs), 7 warps x 16 lags,
// 8 t per lane, 16 iterations of 256 t per warp.
#define LPW   16
#define NWARPS 7
#define THREADS1 (NWARPS * 32)
#define ITERS 16

// Shared memory (dynamic): a = 2112 chunks, b = 2048 chunks (chunk = 16 B = 2 pairs)
#define A_CHUNKS 2112
#define B_CHUNKS 2048
#define A_BYTES  (A_CHUNKS * 16)
#define B_BYTES  (B_CHUNKS * 16)
#define SMEM_TOTAL (A_BYTES + B_BYTES)

// Raw xcorr scratch: 8192 x 112 f32 (~3.67 MB, L2-resident)
__device__ float g_raw[(size_t)NCH * RAWS];

// Swizzle on 16B-chunk index: conflict-free for lane strides of 1/2/4 chunks.
__device__ __forceinline__ int swz(int chunk) {
    return chunk ^ ((chunk >> 3) & 3);
}

__device__ __forceinline__ void fma2(unsigned long long& d,
                                     unsigned long long a, unsigned long long b) {
    asm("fma.rn.f32x2 %0, %1, %2, %0;" : "+l"(d) : "l"(a), "l"(b));
}
__device__ __forceinline__ void unpack2(unsigned long long v, float& lo, float& hi) {
    asm("mov.b64 {%0, %1}, %2;" : "=f"(lo), "=f"(hi) : "l"(v));
}
__device__ __forceinline__ void lds_v2u64(unsigned long long& a, unsigned long long& b,
                                          unsigned addr) {
    asm volatile("ld.shared.v2.u64 {%0, %1}, [%2];" : "=l"(a), "=l"(b) : "r"(addr));
}
__device__ __forceinline__ unsigned smem_u32(const void* p) {
    unsigned r;
    asm("{ .reg .u64 t; cvta.to.shared.u64 t, %1; cvt.u32.u64 %0, t; }" : "=r"(r) : "l"(p));
    return r;
}

// ---------------------------------------------------------------------------
// Stage 1: R[c][l] = sum_t d1[c][t + l - 51] * d2[c][t], l in [0,112)
// Block = channel pair (c0, c0+1). Warp w owns lags [16w, 16w+16).
// Lane handles 8 consecutive t; all FFMA2 operands are natural {c0,c1} pairs.
// ---------------------------------------------------------------------------
__global__ __launch_bounds__(THREADS1, 2)
void xcorr_stage1(const float* __restrict__ d1, const float* __restrict__ d2)
{
    extern __shared__ __align__(16) char smem_raw[];
    float4* a4 = reinterpret_cast<float4*>(smem_raw);
    float4* b4 = reinterpret_cast<float4*>(smem_raw + A_BYTES);

    const int cA  = blockIdx.x * 2;
    const int cB  = cA + 1;
    const int tid = threadIdx.x;

    const float* __restrict__ r1a = d1 + (size_t)cA * NTT;
    const float* __restrict__ r1b = d1 + (size_t)cB * NTT;
    const float* __restrict__ r2a = d2 + (size_t)cA * NTT;
    const float* __restrict__ r2b = d2 + (size_t)cB * NTT;

    // Fill a: pair i holds {d1[cA][i-51], d1[cB][i-51]} (zero outside). Chunk q = pairs 2q,2q+1.
    for (int q = tid; q < A_CHUNKS; q += THREADS1) {
        const int i0 = 2 * q - 51;
        const int i1 = i0 + 1;
        float x0a = 0.f, x0b = 0.f, x1a = 0.f, x1b = 0.f;
        if (i0 >= 0 && i0 < NTT) { x0a = r1a[i0]; x0b = r1b[i0]; }
        if (i1 >= 0 && i1 < NTT) { x1a = r1a[i1]; x1b = r1b[i1]; }
        a4[swz(q)] = make_float4(x0a, x0b, x1a, x1b);
    }
    // Fill b: pair i holds {d2[cA][i], d2[cB][i]}.
    for (int q = tid; q < B_CHUNKS; q += THREADS1) {
        const float2 va = reinterpret_cast<const float2*>(r2a)[q];
        const float2 vb = reinterpret_cast<const float2*>(r2b)[q];
        b4[swz(q)] = make_float4(va.x, vb.x, va.y, vb.y);
    }
    __syncthreads();

    const int warp = tid >> 5;
    const int lane = tid & 31;
    const int lb   = warp * LPW;          // lag base (even)

    const unsigned a_base = smem_u32(smem_raw);
    const unsigned b_base = a_base + A_BYTES;

    // Precompute swizzled addresses; per-iter advance = 128 chunks preserves
    // the swizzle group, so each address just increments by 2048 B.
    unsigned aad[12], bad[4];
    {
        const int ca0 = (lb >> 1) + 4 * lane;   // a chunk base at it=0
#pragma unroll
        for (int j = 0; j < 12; ++j) aad[j] = a_base + ((unsigned)swz(ca0 + j) << 4);
        const int cb0 = 4 * lane;
#pragma unroll
        for (int j = 0; j < 4; ++j)  bad[j] = b_base + ((unsigned)swz(cb0 + j) << 4);
    }

    unsigned long long acc[LPW];
#pragma unroll
    for (int j = 0; j < LPW; ++j) acc[j] = 0ull;

#pragma unroll 1
    for (int it = 0; it < ITERS; ++it) {
        unsigned long long w[24];   // a-pairs [P0, P0+23], P0 = lb + it*256 + 8*lane
        unsigned long long bv[8];   // b-pairs [T0, T0+7],  T0 = it*256 + 8*lane
#pragma unroll
        for (int j = 0; j < 12; ++j) lds_v2u64(w[2 * j], w[2 * j + 1], aad[j]);
#pragma unroll
        for (int j = 0; j < 4; ++j)  lds_v2u64(bv[2 * j], bv[2 * j + 1], bad[j]);

#pragma unroll
        for (int k = 0; k < 8; ++k) {
#pragma unroll
            for (int j = 0; j < LPW; ++j) {
                fma2(acc[j], w[j + k], bv[k]);   // lag lb+j needs pair (lag + t) = P0+j+k
            }
        }

#pragma unroll
        for (int j = 0; j < 12; ++j) aad[j] += 2048u;
#pragma unroll
        for (int j = 0; j < 4; ++j)  bad[j] += 2048u;
    }

    // Lane reduction over t, then lane 0 writes both channels' 16 lags.
    float rl[LPW], rh[LPW];
#pragma unroll
    for (int j = 0; j < LPW; ++j) unpack2(acc[j], rl[j], rh[j]);
#pragma unroll
    for (int j = 0; j < LPW; ++j) {
#pragma unroll
        for (int o = 16; o > 0; o >>= 1) {
            rl[j] += __shfl_xor_sync(0xffffffffu, rl[j], o);
            rh[j] += __shfl_xor_sync(0xffffffffu, rh[j], o);
        }
    }
    if (lane == 0) {
        float* da = g_raw + (size_t)cA * RAWS + lb;
        float* db = g_raw + (size_t)cB * RAWS + lb;
#pragma unroll
        for (int j = 0; j < LPW; ++j) { da[j] = rl[j]; db[j] = rh[j]; }
    }
}

// ---------------------------------------------------------------------------
// Stage 2: moving average over channels (window [c-10, c+9], zero-padded),
// then per-channel argmax|R| / max / min / tmax. Sliding ring over 8 channels.
// ---------------------------------------------------------------------------
#define CPB 8
__global__ __launch_bounds__(128)
void xcorr_stage2(float* __restrict__ out)
{
    __shared__ float sh[CPB][NLAGS + 1];
    const int c0  = blockIdx.x * CPB;
    const int tid = threadIdx.x;

    if (tid < NLAGS) {
        float ring[20];
        float s = 0.0f;
#pragma unroll
        for (int i = 0; i < CPB + 19; ++i) {
            const int ch = c0 - 10 + i;
            float x = 0.0f;
            if (ch >= 0 && ch < NCH) x = g_raw[(size_t)ch * RAWS + tid];
            s += x;
            if (i >= 20) s -= ring[i % 20];
            ring[i % 20] = x;
            const int cc = i - 19;
            if (cc >= 0) {
                const float m = s * (1.0f / 20.0f);
                sh[cc][tid] = m;
                out[(size_t)(c0 + cc) * NLAGS + tid] = m;
            }
        }
    }
    __syncthreads();

    const int warp = tid >> 5;
    const int lane = tid & 31;

    for (int cc = warp; cc < CPB; cc += 4) {
        float bestAbs = -1.0f;
        int   bestIdx = 0;
        float bestVal = 0.0f;
        float vpos = -3.402823466e38f;
        float vneg =  3.402823466e38f;

        for (int l = lane; l < NLAGS; l += 32) {
            const float v  = sh[cc][l];
            const float av = fabsf(v);
            if (av > bestAbs) { bestAbs = av; bestIdx = l; bestVal = v; }
            vpos = fmaxf(vpos, v);
            vneg = fminf(vneg, v);
        }
#pragma unroll
        for (int o = 16; o > 0; o >>= 1) {
            const float oa = __shfl_down_sync(0xffffffffu, bestAbs, o);
            const int   oi = __shfl_down_sync(0xffffffffu, bestIdx, o);
            const float ov = __shfl_down_sync(0xffffffffu, bestVal, o);
            if (oa > bestAbs || (oa == bestAbs && oi < bestIdx)) {
                bestAbs = oa; bestIdx = oi; bestVal = ov;
            }
            vpos = fmaxf(vpos, __shfl_down_sync(0xffffffffu, vpos, o));
            vneg = fminf(vneg, __shfl_down_sync(0xffffffffu, vneg, o));
        }

        if (lane == 0) {
            const int   ch    = c0 + cc;
            const float vside = (bestVal >= 0.0f) ? vneg : vpos;
            out[(size_t)XCOR_N + ch]           = bestVal;
            out[(size_t)XCOR_N + NCH + ch]     = vside;
            out[(size_t)XCOR_N + 2 * NCH + ch] = (float)(bestIdx - 51) * 0.01f;
        }
    }
}

// ---------------------------------------------------------------------------
// kernel_launch
// ---------------------------------------------------------------------------
extern "C" void kernel_launch(void* const* d_in, const int* in_sizes, int n_in,
                              void* d_out, int out_size)
{
    const float* data1 = (const float*)d_in[0];
    const float* data2 = (const float*)d_in[1];
    float* out = (float*)d_out;

    cudaFuncSetAttribute(xcorr_stage1,
                         cudaFuncAttributeMaxDynamicSharedMemorySize, SMEM_TOTAL);

    xcorr_stage1<<<NCH / 2, THREADS1, SMEM_TOTAL>>>(data1, data2);
    xcorr_stage2<<<NCH / CPB, 128>>>(out);
}